// round 7
// baseline (speedup 1.0000x reference)
#include <cuda_runtime.h>

#define HDIM 50
#define TLEN 512
#define NBATCH 4096
#define LANES 32               // batches per CTA (= lanes per warp)
#define UPT 2                  // units per thread
#define UG 25                  // unit groups (warps per CTA)
#define NTH (LANES*UG)         // 800 threads
#define NCTA (NBATCH/LANES)    // 128 CTAs
#define WSZ (4*HDIM*HDIM)      // 10000 floats per weight matrix
#define HB (HDIM*LANES)        // 1600 floats per h buffer

typedef unsigned long long u64;

__device__ __forceinline__ u64 pk2(float lo, float hi) {
    u64 r; asm("mov.b64 %0, {%1,%2};" : "=l"(r) : "f"(lo), "f"(hi)); return r;
}
__device__ __forceinline__ void upk2(u64 v, float& lo, float& hi) {
    asm("mov.b64 {%0,%1}, %2;" : "=f"(lo), "=f"(hi) : "l"(v));
}
// packed fp32x2 FMA (Blackwell 2x fp32 path; only reachable via PTX)
__device__ __forceinline__ u64 ffma2(u64 a, u64 b, u64 c) {
    u64 d; asm("fma.rn.f32x2 %0, %1, %2, %3;" : "=l"(d) : "l"(a), "l"(b), "l"(c)); return d;
}

__device__ __forceinline__ float sigf(float z) {
    return __fdividef(1.0f, 1.0f + __expf(-z));
}
__device__ __forceinline__ float tanhfast(float z) {
    return fmaf(2.0f, sigf(2.0f * z), -1.0f);
}

__device__ __forceinline__ void cellupd(u64 aif, u64 ago, float& c, float& h) {
    float zi, zf, zg, zo;
    upk2(aif, zi, zf);
    upk2(ago, zg, zo);
    float ig = sigf(zi);
    float fg = sigf(zf);
    float gg = tanhfast(zg);
    float og = sigf(zo);
    c = fmaf(fg, c, ig * gg);
    h = og * tanhfast(c);
}

// smem layout (float offsets):
//  W0  [u][k][4g]  10000   (ulonglong2 rows, warp-uniform broadcast reads)
//  W1i             10000
//  W1h             10000
//  hs0 [2][50][32]  3200   (double-buffered, coalesced [k][lane])
//  hs1 [2][50][32]  3200
//  xs  [32]           32
//  bA  u64[2][50]    200
//  bB  u64[2][50]    200
//  w0t u64[2][50]    200
#define SM_W0   0
#define SM_W1I  10000
#define SM_W1H  20000
#define SM_H0   30000
#define SM_H1   33200
#define SM_XS   36400
#define SM_BA   36432
#define SM_BB   36632
#define SM_W0T  36832
#define SM_TOT  37032

__global__ void __launch_bounds__(NTH, 1)
lstm_kernel(const float* __restrict__ x,
            const float* __restrict__ w_ih0, const float* __restrict__ w_hh0,
            const float* __restrict__ b_ih0, const float* __restrict__ b_hh0,
            const float* __restrict__ w_ih1, const float* __restrict__ w_hh1,
            const float* __restrict__ b_ih1, const float* __restrict__ b_hh1,
            const float* __restrict__ fc_w,  const float* __restrict__ fc_b,
            float* __restrict__ out) {
    extern __shared__ float smem[];
    float* xs = smem + SM_XS;

    const int tid  = threadIdx.x;
    const int lane = tid & 31;        // batch within CTA
    const int grp  = tid >> 5;        // unit group
    const int u0   = grp * UPT;
    const int b0   = blockIdx.x * LANES;

    // ---- stage weights transposed: [u][k][4 gates] ----
    for (int i = tid; i < WSZ; i += NTH) {
        int r = i / HDIM;             // r = g*H + uu
        int k = i % HDIM;
        int g = r / HDIM;
        int uu = r % HDIM;
        int o = (uu * HDIM + k) * 4 + g;
        smem[SM_W0  + o] = w_hh0[i];
        smem[SM_W1I + o] = w_ih1[i];
        smem[SM_W1H + o] = w_hh1[i];
    }
    // ---- stage biases / layer0 input weights as gate-pair u64 tables ----
    if (tid < HDIM) {
        int u = tid;
        u64* bA  = (u64*)(smem + SM_BA);
        u64* bB  = (u64*)(smem + SM_BB);
        u64* w0t = (u64*)(smem + SM_W0T);
#pragma unroll
        for (int p = 0; p < 2; p++) {
            int g0 = 2 * p, g1 = 2 * p + 1;
            bA[p * HDIM + u]  = pk2(b_ih0[g0 * HDIM + u] + b_hh0[g0 * HDIM + u],
                                    b_ih0[g1 * HDIM + u] + b_hh0[g1 * HDIM + u]);
            bB[p * HDIM + u]  = pk2(b_ih1[g0 * HDIM + u] + b_hh1[g0 * HDIM + u],
                                    b_ih1[g1 * HDIM + u] + b_hh1[g1 * HDIM + u]);
            w0t[p * HDIM + u] = pk2(w_ih0[g0 * HDIM + u], w_ih0[g1 * HDIM + u]);
        }
    }
    // zero both h double-buffers (contiguous hs0,hs1 region)
    for (int i = tid; i < 2 * HB * 2; i += NTH) smem[SM_H0 + i] = 0.0f;
    if (tid < LANES) xs[tid] = x[(size_t)(b0 + tid) * TLEN];
    __syncthreads();

    const ulonglong2* W0p  = (const ulonglong2*)(smem + SM_W0);
    const ulonglong2* W1ip = (const ulonglong2*)(smem + SM_W1I);
    const ulonglong2* W1hp = (const ulonglong2*)(smem + SM_W1H);
    const u64* bAp  = (const u64*)(smem + SM_BA);
    const u64* bBp  = (const u64*)(smem + SM_BB);
    const u64* w0tp = (const u64*)(smem + SM_W0T);

    float c0[UPT], c1[UPT], hn1[UPT];
#pragma unroll
    for (int j = 0; j < UPT; j++) { c0[j] = 0.0f; c1[j] = 0.0f; hn1[j] = 0.0f; }

    int cur = 0;
#pragma unroll 1
    for (int t = 0; t < TLEN; t++) {
        const int nxt = cur ^ 1;
        const float* h0c = smem + SM_H0 + cur * HB;   // h0(t-1)
        float*       h0n = smem + SM_H0 + nxt * HB;   // h0(t)
        const float* h1c = smem + SM_H1 + cur * HB;   // h1(t-1)
        float*       h1n = smem + SM_H1 + nxt * HB;   // h1(t)

        // ===== Phase A: layer 0 =====
        float xv = xs[lane];
        u64 xp = pk2(xv, xv);
        u64 aif[UPT], ago[UPT];
#pragma unroll
        for (int j = 0; j < UPT; j++) {
            aif[j] = ffma2(w0tp[u0 + j],        xp, bAp[u0 + j]);
            ago[j] = ffma2(w0tp[HDIM + u0 + j], xp, bAp[HDIM + u0 + j]);
        }
#pragma unroll
        for (int k = 0; k < HDIM; k++) {
            float hv = h0c[k * LANES + lane];
            u64 hp = pk2(hv, hv);
#pragma unroll
            for (int j = 0; j < UPT; j++) {
                ulonglong2 w = W0p[(u0 + j) * HDIM + k];
                aif[j] = ffma2(w.x, hp, aif[j]);
                ago[j] = ffma2(w.y, hp, ago[j]);
            }
        }
#pragma unroll
        for (int j = 0; j < UPT; j++) {
            float hn;
            cellupd(aif[j], ago[j], c0[j], hn);
            h0n[(u0 + j) * LANES + lane] = hn;
        }
        __syncthreads();

        // ===== Phase B: layer 1 over h0(t) [nxt] + h1(t-1) [cur] =====
#pragma unroll
        for (int j = 0; j < UPT; j++) {
            aif[j] = bBp[u0 + j];
            ago[j] = bBp[HDIM + u0 + j];
        }
#pragma unroll
        for (int k = 0; k < HDIM; k++) {
            float hv0 = h0n[k * LANES + lane];
            float hv1 = h1c[k * LANES + lane];
            u64 hp0 = pk2(hv0, hv0);
            u64 hp1 = pk2(hv1, hv1);
#pragma unroll
            for (int j = 0; j < UPT; j++) {
                ulonglong2 wi = W1ip[(u0 + j) * HDIM + k];
                aif[j] = ffma2(wi.x, hp0, aif[j]);
                ago[j] = ffma2(wi.y, hp0, ago[j]);
                ulonglong2 wh = W1hp[(u0 + j) * HDIM + k];
                aif[j] = ffma2(wh.x, hp1, aif[j]);
                ago[j] = ffma2(wh.y, hp1, ago[j]);
            }
        }
#pragma unroll
        for (int j = 0; j < UPT; j++) {
            cellupd(aif[j], ago[j], c1[j], hn1[j]);
            h1n[(u0 + j) * LANES + lane] = hn1[j];
        }
        // stage x(t+1) (all xs reads happened in Phase A, before sync #1)
        if (tid < LANES && (t + 1) < TLEN)
            xs[tid] = x[(size_t)(b0 + tid) * TLEN + (t + 1)];
        __syncthreads();
        cur = nxt;
    }

    // ===== FC epilogue: out[b] = fc_w . h1(T-1)[b] + fc_b =====
    {
        float p = fc_w[u0] * hn1[0] + fc_w[u0 + 1] * hn1[1];
        float* red = smem + SM_H0;           // reuse as [grp][lane] scratch
        red[grp * LANES + lane] = p;
        __syncthreads();
        if (tid < LANES) {
            float s = fc_b[0];
#pragma unroll
            for (int g = 0; g < UG; g++) s += red[g * LANES + tid];
            out[b0 + tid] = s;
        }
    }
}

extern "C" void kernel_launch(void* const* d_in, const int* in_sizes, int n_in,
                              void* d_out, int out_size) {
    const float* x     = (const float*)d_in[0];
    const float* w_ih0 = (const float*)d_in[1];
    const float* w_hh0 = (const float*)d_in[2];
    const float* b_ih0 = (const float*)d_in[3];
    const float* b_hh0 = (const float*)d_in[4];
    const float* w_ih1 = (const float*)d_in[5];
    const float* w_hh1 = (const float*)d_in[6];
    const float* b_ih1 = (const float*)d_in[7];
    const float* b_hh1 = (const float*)d_in[8];
    const float* fc_w  = (const float*)d_in[9];
    const float* fc_b  = (const float*)d_in[10];
    float* out = (float*)d_out;

    const size_t smem_bytes = SM_TOT * sizeof(float);
    cudaFuncSetAttribute(lstm_kernel, cudaFuncAttributeMaxDynamicSharedMemorySize,
                         (int)smem_bytes);
    lstm_kernel<<<NCTA, NTH, smem_bytes>>>(x, w_ih0, w_hh0, b_ih0, b_hh0,
                                           w_ih1, w_hh1, b_ih1, b_hh1,
                                           fc_w, fc_b, out);
}